// round 8
// baseline (speedup 1.0000x reference)
#include <cuda_runtime.h>
#include <cuda_bf16.h>
#include <cstdint>

// Shapes fixed by setup_inputs: L=4, B=8, C=256, H=64, W=64
#define L_DIM 4
#define B_DIM 8
#define C_DIM 256
#define SPATIAL 4096
#define S4 (SPATIAL / 4)                 // 1024 float4 per slab
#define SLABS_PER_B (L_DIM * C_DIM)      // 1024 slabs per batch
#define PAIRS_PER_B (SLABS_PER_B / 2)    // 512 pair-tickets per batch
#define BPG 74                           // blocks per batch-group
#define GRID_X (B_DIM * BPG)             // 592 = 148 SMs * 4 blocks (one wave)
#define INV_SPATIAL (1.0f / 4096.0f)

// Cross-block state (allocation-free rule -> __device__ globals, zero-init).
__device__ float    g_gap [B_DIM][SLABS_PER_B];
__device__ float    g_attn[B_DIM][SLABS_PER_B];
__device__ unsigned g_t1[B_DIM];         // phase-1 steal tickets
__device__ unsigned g_t2[B_DIM];         // phase-3 steal tickets
__device__ unsigned g_gap_done[B_DIM];
__device__ unsigned g_attn_done[B_DIM];
__device__ unsigned g_exit_count;

__global__ __launch_bounds__(256) void sffm_fused(const float* __restrict__ in,
                                                  const float* __restrict__ Wm,
                                                  float* __restrict__ out) {
    const int bid  = blockIdx.x;
    const int b    = bid / BPG;          // batch group — all groups concurrent
    const int j    = bid - b * BPG;      // block index within group (phase 2)
    const int t    = threadIdx.x;
    const int lane = t & 31;
    const int warp = t >> 5;

    __shared__ float    gap_sm[L_DIM * C_DIM];  // 4 KB staged gap
    __shared__ float    ws[2][8];
    __shared__ unsigned sm_ticket;

    const float4* in4  = (const float4*)in;
    float4*       out4 = (float4*)out;

    // ============ Phase 1: GAP via per-batch pair-stealing ============
    for (;;) {
        if (t == 0) sm_ticket = atomicAdd(&g_t1[b], 1u);
        __syncthreads();
        unsigned tk = sm_ticket;
        __syncthreads();                 // protect sm_ticket reuse
        if (tk >= PAIRS_PER_B) break;
        int s0 = 2 * tk, s1 = s0 + 1;    // adjacent slabs: 32 KB contiguous
        int l0 = s0 >> 8, c0 = s0 & 255;
        int l1 = s1 >> 8, c1 = s1 & 255;
        size_t base0 = ((size_t)((l0 * B_DIM + b) * C_DIM + c0)) * S4;
        size_t base1 = ((size_t)((l1 * B_DIM + b) * C_DIM + c1)) * S4;
        float4 v0[4], v1[4];
#pragma unroll
        for (int i = 0; i < 4; i++) v0[i] = in4[base0 + t + i * 256];
#pragma unroll
        for (int i = 0; i < 4; i++) v1[i] = in4[base1 + t + i * 256];
        float r0 = 0.f, r1 = 0.f;
#pragma unroll
        for (int i = 0; i < 4; i++) {
            r0 += (v0[i].x + v0[i].y) + (v0[i].z + v0[i].w);
            r1 += (v1[i].x + v1[i].y) + (v1[i].z + v1[i].w);
        }
#pragma unroll
        for (int o = 16; o; o >>= 1) {
            r0 += __shfl_xor_sync(0xffffffffu, r0, o);
            r1 += __shfl_xor_sync(0xffffffffu, r1, o);
        }
        if (lane == 0) { ws[0][warp] = r0; ws[1][warp] = r1; }
        __syncthreads();
        if (t == 0) {
            float a0 = 0.f, a1 = 0.f;
#pragma unroll
            for (int w = 0; w < 8; w++) { a0 += ws[0][w]; a1 += ws[1][w]; }
            g_gap[b][s0] = a0 * INV_SPATIAL;
            g_gap[b][s1] = a1 * INV_SPATIAL;
        }
    }
    if (t == 0) { __threadfence(); atomicAdd(&g_gap_done[b], 1u); }

    // ---- barrier 1: this batch's GAP complete ----
    if (t == 0) {
        while (*(volatile unsigned*)&g_gap_done[b] < BPG) __nanosleep(64);
        __threadfence();
    }
    __syncthreads();

    for (int i = t; i < L_DIM * C_DIM; i += 256) gap_sm[i] = g_gap[b][i];
    __syncthreads();

    // ============ Phase 2: attn for static slab set -> g_attn ============
    int nslab = 0;
    for (int s = j; s < SLABS_PER_B; s += BPG) nslab++;   // 13 or 14
    for (int k = warp; k < nslab; k += 8) {
        int s = j + k * BPG;
        int lsel = s >> 8, q = s & 255;
        const float4* wr = (const float4*)(Wm + (size_t)q * C_DIM);
        const float4* g4 = (const float4*)gap_sm;
        float s0 = 0.f, s1 = 0.f, s2 = 0.f, s3 = 0.f;
#pragma unroll
        for (int ii = 0; ii < 2; ii++) {
            int i = lane + ii * 32;
            float4 wv = wr[i];
            float4 a0 = g4[0 * 64 + i];
            float4 a1 = g4[1 * 64 + i];
            float4 a2 = g4[2 * 64 + i];
            float4 a3 = g4[3 * 64 + i];
            s0 += wv.x * a0.x + wv.y * a0.y + wv.z * a0.z + wv.w * a0.w;
            s1 += wv.x * a1.x + wv.y * a1.y + wv.z * a1.z + wv.w * a1.w;
            s2 += wv.x * a2.x + wv.y * a2.y + wv.z * a2.z + wv.w * a2.w;
            s3 += wv.x * a3.x + wv.y * a3.y + wv.z * a3.z + wv.w * a3.w;
        }
#pragma unroll
        for (int o = 16; o; o >>= 1) {
            s0 += __shfl_xor_sync(0xffffffffu, s0, o);
            s1 += __shfl_xor_sync(0xffffffffu, s1, o);
            s2 += __shfl_xor_sync(0xffffffffu, s2, o);
            s3 += __shfl_xor_sync(0xffffffffu, s3, o);
        }
        if (lane == 0) {
            float m  = fmaxf(fmaxf(s0, s1), fmaxf(s2, s3));
            float e0 = __expf(s0 - m), e1 = __expf(s1 - m);
            float e2 = __expf(s2 - m), e3 = __expf(s3 - m);
            float inv = 1.0f / (e0 + e1 + e2 + e3);
            float sel = (lsel == 0) ? e0 : (lsel == 1) ? e1 : (lsel == 2) ? e2 : e3;
            g_attn[b][s] = sel * inv;
        }
    }
    if (t == 0) { __threadfence(); atomicAdd(&g_attn_done[b], 1u); }

    // ---- barrier 2: this batch's attn table complete (cheap: equal work) ----
    if (t == 0) {
        while (*(volatile unsigned*)&g_attn_done[b] < BPG) __nanosleep(64);
        __threadfence();
    }
    __syncthreads();

    // ============ Phase 3: scale via pair-stealing (L2-hot re-read) ============
    for (;;) {
        if (t == 0) sm_ticket = atomicAdd(&g_t2[b], 1u);
        __syncthreads();
        unsigned tk = sm_ticket;
        __syncthreads();
        if (tk >= PAIRS_PER_B) break;
        int s0 = 2 * tk, s1 = s0 + 1;
        float a0 = __ldg(&g_attn[b][s0]);
        float a1 = __ldg(&g_attn[b][s1]);
        int l0 = s0 >> 8, c0 = s0 & 255;
        int l1 = s1 >> 8, c1 = s1 & 255;
        size_t base0 = ((size_t)((l0 * B_DIM + b) * C_DIM + c0)) * S4;
        size_t base1 = ((size_t)((l1 * B_DIM + b) * C_DIM + c1)) * S4;
#pragma unroll
        for (int i = 0; i < 4; i++) {
            float4 v = __ldcs(in4 + base0 + t + i * 256);
            v.x *= a0; v.y *= a0; v.z *= a0; v.w *= a0;
            __stcs(out4 + base0 + t + i * 256, v);
        }
#pragma unroll
        for (int i = 0; i < 4; i++) {
            float4 v = __ldcs(in4 + base1 + t + i * 256);
            v.x *= a1; v.y *= a1; v.z *= a1; v.w *= a1;
            __stcs(out4 + base1 + t + i * 256, v);
        }
    }

    // ---- reset cross-launch state (last block out; graph-replay safe) ----
    __syncthreads();
    if (t == 0) {
        __threadfence();
        unsigned v = atomicAdd(&g_exit_count, 1u);
        if (v == GRID_X - 1) {
#pragma unroll
            for (int i = 0; i < B_DIM; i++) {
                g_t1[i] = 0; g_t2[i] = 0;
                g_gap_done[i] = 0; g_attn_done[i] = 0;
            }
            __threadfence();
            g_exit_count = 0;
        }
    }
}

extern "C" void kernel_launch(void* const* d_in, const int* in_sizes, int n_in,
                              void* d_out, int out_size) {
    const float* in  = (const float*)d_in[0];   // [L,B,C,H,W]
    const float* Wm  = (const float*)d_in[1];   // [C,C]
    float*       out = (float*)d_out;           // [L,B,C,H,W]

    sffm_fused<<<GRID_X, 256>>>(in, Wm, out);
}

// round 11
// speedup vs baseline: 1.0789x; 1.0789x over previous
#include <cuda_runtime.h>
#include <cuda_bf16.h>
#include <cstdint>

// Shapes fixed by setup_inputs: L=4, B=8, C=256, H=64, W=64
#define L_DIM 4
#define B_DIM 8
#define C_DIM 256
#define SPATIAL 4096
#define S4 (SPATIAL / 4)                 // 1024 float4 per slab
#define SLABS_PER_B (L_DIM * C_DIM)      // 1024 slabs per batch
#define BPG 128                          // blocks per batch-group
#define SLABS_PER_BLK 8                  // 1024 / 128 — exact
#define GRID_X (B_DIM * BPG)             // 1024 blocks (<= 148*8 = 1184 resident)
#define NTHR 128
#define INV_SPATIAL (1.0f / 4096.0f)

// Cross-block state (allocation-free rule -> __device__ globals, zero-init).
__device__ float    g_gap[B_DIM][SLABS_PER_B];
__device__ unsigned g_gap_done[B_DIM];
__device__ unsigned g_exit_count;

__global__ __launch_bounds__(NTHR, 8) void sffm_fused(const float* __restrict__ in,
                                                      const float* __restrict__ Wm,
                                                      float* __restrict__ out) {
    const int bid  = blockIdx.x;
    const int b    = bid >> 7;           // batch group (all concurrent)
    const int j    = bid & 127;          // block within group
    const int t    = threadIdx.x;
    const int lane = t & 31;
    const int warp = t >> 5;             // 0..3, owns slabs {j*8+2w, j*8+2w+1}

    __shared__ float gap_sm[L_DIM * C_DIM];   // 4 KB staged gap for batch b

    const float4* in4  = (const float4*)in;
    float4*       out4 = (float4*)out;

    // This block's 8 slabs are contiguous: s in [j*8, j*8+8), all same l
    // (j*8 mod 256 <= 248 so no l-boundary crossing).
    const int s0 = j * SLABS_PER_BLK + 2 * warp;     // this warp's first slab
    const int l  = s0 >> 8;
    const int c0 = s0 & 255;
    const size_t base0 = ((size_t)((l * B_DIM + b) * C_DIM + c0)) * S4;
    const size_t base1 = base0 + S4;                 // slab s0+1, contiguous

    // ======== Phase 1: GAP — warp covers FULL 1024-float4 slab (32 iters) ======
    {
        float r0 = 0.f, r1 = 0.f;
#pragma unroll 4
        for (int i = 0; i < 32; i++) {           // 2 streams -> 8 loads in flight
            float4 v0 = in4[base0 + lane + i * 32];
            float4 v1 = in4[base1 + lane + i * 32];
            r0 += (v0.x + v0.y) + (v0.z + v0.w);
            r1 += (v1.x + v1.y) + (v1.z + v1.w);
        }
#pragma unroll
        for (int o = 16; o; o >>= 1) {
            r0 += __shfl_xor_sync(0xffffffffu, r0, o);
            r1 += __shfl_xor_sync(0xffffffffu, r1, o);
        }
        if (lane == 0) {
            g_gap[b][s0]     = r0 * INV_SPATIAL;
            g_gap[b][s0 + 1] = r1 * INV_SPATIAL;
        }
    }
    __syncthreads();                      // all 4 warps' gap writes issued
    if (t == 0) { __threadfence(); atomicAdd(&g_gap_done[b], 1u); }

    // ---- barrier: this batch's 128 blocks finished GAP ----
    if (t == 0) {
        while (*(volatile unsigned*)&g_gap_done[b] < BPG) __nanosleep(64);
        __threadfence();
    }
    __syncthreads();

    // stage batch-b gap into smem (4 KB; source is L2-hot)
#pragma unroll
    for (int i = 0; i < 8; i++) gap_sm[t + i * NTHR] = g_gap[b][t + i * NTHR];
    __syncthreads();

    // ====== Phase 2: attn scalars for this warp's 2 slabs — stays in regs ======
    float attn[2];
#pragma unroll
    for (int p = 0; p < 2; p++) {
        int q = c0 + p;                   // output channel = slab's c
        const float4* wr = (const float4*)(Wm + (size_t)q * C_DIM);
        const float4* g4 = (const float4*)gap_sm;
        float sc0 = 0.f, sc1 = 0.f, sc2 = 0.f, sc3 = 0.f;
#pragma unroll
        for (int ii = 0; ii < 2; ii++) {
            int i = lane + ii * 32;
            float4 wv = wr[i];
            float4 a0 = g4[0 * 64 + i];
            float4 a1 = g4[1 * 64 + i];
            float4 a2 = g4[2 * 64 + i];
            float4 a3 = g4[3 * 64 + i];
            sc0 += wv.x * a0.x + wv.y * a0.y + wv.z * a0.z + wv.w * a0.w;
            sc1 += wv.x * a1.x + wv.y * a1.y + wv.z * a1.z + wv.w * a1.w;
            sc2 += wv.x * a2.x + wv.y * a2.y + wv.z * a2.z + wv.w * a2.w;
            sc3 += wv.x * a3.x + wv.y * a3.y + wv.z * a3.z + wv.w * a3.w;
        }
#pragma unroll
        for (int o = 16; o; o >>= 1) {
            sc0 += __shfl_xor_sync(0xffffffffu, sc0, o);
            sc1 += __shfl_xor_sync(0xffffffffu, sc1, o);
            sc2 += __shfl_xor_sync(0xffffffffu, sc2, o);
            sc3 += __shfl_xor_sync(0xffffffffu, sc3, o);
        }
        // every lane has all 4 scores -> softmax locally, attn stays in regs
        float m  = fmaxf(fmaxf(sc0, sc1), fmaxf(sc2, sc3));
        float e0 = __expf(sc0 - m), e1 = __expf(sc1 - m);
        float e2 = __expf(sc2 - m), e3 = __expf(sc3 - m);
        float inv = 1.0f / (e0 + e1 + e2 + e3);
        float sel = (l == 0) ? e0 : (l == 1) ? e1 : (l == 2) ? e2 : e3;
        attn[p] = sel * inv;
    }

    // ===== Phase 3: scale own 2 slabs, full coverage (L2-hot re-read) =====
    {
        float a0 = attn[0], a1 = attn[1];
#pragma unroll 4
        for (int i = 0; i < 32; i++) {
            float4 v0 = __ldcs(in4 + base0 + lane + i * 32);
            float4 v1 = __ldcs(in4 + base1 + lane + i * 32);
            v0.x *= a0; v0.y *= a0; v0.z *= a0; v0.w *= a0;
            v1.x *= a1; v1.y *= a1; v1.z *= a1; v1.w *= a1;
            __stcs(out4 + base0 + lane + i * 32, v0);
            __stcs(out4 + base1 + lane + i * 32, v1);
        }
    }

    // ---- reset cross-launch state (last block out; graph-replay safe) ----
    __syncthreads();
    if (t == 0) {
        __threadfence();
        unsigned v = atomicAdd(&g_exit_count, 1u);
        if (v == GRID_X - 1) {
#pragma unroll
            for (int i = 0; i < B_DIM; i++) g_gap_done[i] = 0;
            __threadfence();
            g_exit_count = 0;
        }
    }
}

extern "C" void kernel_launch(void* const* d_in, const int* in_sizes, int n_in,
                              void* d_out, int out_size) {
    const float* in  = (const float*)d_in[0];   // [L,B,C,H,W]
    const float* Wm  = (const float*)d_in[1];   // [C,C]
    float*       out = (float*)d_out;           // [L,B,C,H,W]

    sffm_fused<<<GRID_X, NTHR>>>(in, Wm, out);
}